// round 2
// baseline (speedup 1.0000x reference)
#include <cuda_runtime.h>
#include <cuda_bf16.h>
#include <math.h>

// Problem constants
#define Bq   4
#define Lq   4096
#define Dq   1024
#define Hq   16
#define Wq   64
#define HDq  64
#define Mrows (Bq*Lq)          // 16384

// Scratch buffers (device globals; allocation is forbidden)
__device__ float g_qkv[(size_t)Mrows * 3 * Dq];   // 192 MB
__device__ float g_attn[(size_t)Mrows * Dq];      // 64 MB
__device__ float g_y[(size_t)Mrows * Dq];         // 64 MB

// ---------------------------------------------------------------------------
// SGEMM (NT): C[m][n] = sum_k A[m][k] * B[n][k] + bias[n] (+ res[m][n])
// A: MxK row-major, B: NxK row-major. Tiles 128x128x16, 256 thr, 8x8 microtile.
// ---------------------------------------------------------------------------
#define BM 128
#define BN 128
#define BK 16

__global__ __launch_bounds__(256, 1)
void sgemm_nt(const float* __restrict__ A, const float* __restrict__ B,
              const float* __restrict__ bias, const float* __restrict__ res,
              float* __restrict__ C, int M, int N, int K)
{
    __shared__ float As[BK][BM];
    __shared__ float Bs[BK][BN];

    const int tid = threadIdx.x;
    const int bn = blockIdx.x;   // N tile
    const int bm = blockIdx.y;   // M tile
    const int ty = tid >> 4;     // 0..15
    const int tx = tid & 15;     // 0..15

    const float* Ab = A + (size_t)bm * BM * K;
    const float* Bb = B + (size_t)bn * BN * K;

    float acc[8][8];
    #pragma unroll
    for (int i = 0; i < 8; i++)
        #pragma unroll
        for (int j = 0; j < 8; j++) acc[i][j] = 0.f;

    for (int k0 = 0; k0 < K; k0 += BK) {
        // Load tiles: 128 rows x 16 k = 512 float4 per matrix
        #pragma unroll
        for (int f = tid; f < 512; f += 256) {
            int row = f >> 2;
            int kq  = (f & 3) << 2;
            float4 va = *(const float4*)(Ab + (size_t)row * K + k0 + kq);
            As[kq + 0][row] = va.x; As[kq + 1][row] = va.y;
            As[kq + 2][row] = va.z; As[kq + 3][row] = va.w;
            float4 vb = *(const float4*)(Bb + (size_t)row * K + k0 + kq);
            Bs[kq + 0][row] = vb.x; Bs[kq + 1][row] = vb.y;
            Bs[kq + 2][row] = vb.z; Bs[kq + 3][row] = vb.w;
        }
        __syncthreads();

        #pragma unroll
        for (int k = 0; k < BK; k++) {
            float a[8], b[8];
            *(float4*)(a)     = *(const float4*)&As[k][ty * 8];
            *(float4*)(a + 4) = *(const float4*)&As[k][ty * 8 + 4];
            *(float4*)(b)     = *(const float4*)&Bs[k][tx * 8];
            *(float4*)(b + 4) = *(const float4*)&Bs[k][tx * 8 + 4];
            #pragma unroll
            for (int i = 0; i < 8; i++)
                #pragma unroll
                for (int j = 0; j < 8; j++)
                    acc[i][j] = fmaf(a[i], b[j], acc[i][j]);
        }
        __syncthreads();
    }

    // Epilogue: bias (+ residual)
    const int colb = bn * BN + tx * 8;
    float bi[8];
    #pragma unroll
    for (int j = 0; j < 8; j++) bi[j] = bias[colb + j];

    #pragma unroll
    for (int i = 0; i < 8; i++) {
        const int row = bm * BM + ty * 8 + i;
        float* Cr = C + (size_t)row * N + colb;
        if (res) {
            const float* Rr = res + (size_t)row * N + colb;
            #pragma unroll
            for (int j = 0; j < 8; j += 4) {
                float4 r = *(const float4*)(Rr + j);
                float4 o;
                o.x = acc[i][j + 0] + bi[j + 0] + r.x;
                o.y = acc[i][j + 1] + bi[j + 1] + r.y;
                o.z = acc[i][j + 2] + bi[j + 2] + r.z;
                o.w = acc[i][j + 3] + bi[j + 3] + r.w;
                *(float4*)(Cr + j) = o;
            }
        } else {
            #pragma unroll
            for (int j = 0; j < 8; j += 4) {
                float4 o;
                o.x = acc[i][j + 0] + bi[j + 0];
                o.y = acc[i][j + 1] + bi[j + 1];
                o.z = acc[i][j + 2] + bi[j + 2];
                o.w = acc[i][j + 3] + bi[j + 3];
                *(float4*)(Cr + j) = o;
            }
        }
    }
}

// ---------------------------------------------------------------------------
// Windowed attention: one CTA per (b, h, window). 128 threads.
// smem: Q/V buffer [64][64], K transposed [64][65], S [64][65]  (~48.5 KB)
// ---------------------------------------------------------------------------
#define SMEM_ATTN ((4096 + 64 * 65 + 64 * 65) * 4)

__global__ __launch_bounds__(128, 1)
void win_attn(const float* __restrict__ qkv, float* __restrict__ outp)
{
    extern __shared__ float sm[];
    float* QV = sm;                 // [64][64]: Q during phase 1-2, V after
    float* Kt = sm + 4096;          // [64][65] transposed: Kt[d][l]
    float* S  = sm + 4096 + 64*65;  // [64][65]

    const int tid = threadIdx.x;
    const int w = blockIdx.x & 63;
    const int h = (blockIdx.x >> 6) & 15;
    const int b = blockIdx.x >> 10;

    const size_t base = ((size_t)(b * Lq + w * Wq)) * (3 * Dq) + h * HDq;

    // Load Q (row-major) and K (transposed, padded)
    #pragma unroll
    for (int f = tid; f < 1024; f += 128) {
        int row = f >> 4;
        int dq  = (f & 15) << 2;
        size_t g = base + (size_t)row * (3 * Dq) + dq;
        *(float4*)(QV + row * 64 + dq) = *(const float4*)(qkv + g);
        float4 kv = *(const float4*)(qkv + g + Dq);
        Kt[(dq + 0) * 65 + row] = kv.x;
        Kt[(dq + 1) * 65 + row] = kv.y;
        Kt[(dq + 2) * 65 + row] = kv.z;
        Kt[(dq + 3) * 65 + row] = kv.w;
    }
    __syncthreads();

    const int r0 = (tid >> 4) << 3;  // 8 rows per thread
    const int c0 = (tid & 15) << 2;  // 4 cols per thread

    // S = Q K^T * scale
    float acc[8][4];
    #pragma unroll
    for (int i = 0; i < 8; i++)
        #pragma unroll
        for (int j = 0; j < 4; j++) acc[i][j] = 0.f;

    #pragma unroll 4
    for (int k = 0; k < 64; k++) {
        float a[8], bb[4];
        #pragma unroll
        for (int i = 0; i < 8; i++) a[i] = QV[(r0 + i) * 64 + k];
        #pragma unroll
        for (int j = 0; j < 4; j++) bb[j] = Kt[k * 65 + c0 + j];
        #pragma unroll
        for (int i = 0; i < 8; i++)
            #pragma unroll
            for (int j = 0; j < 4; j++)
                acc[i][j] = fmaf(a[i], bb[j], acc[i][j]);
    }
    const float scale = 0.125f;  // 1/sqrt(64)
    #pragma unroll
    for (int i = 0; i < 8; i++)
        #pragma unroll
        for (int j = 0; j < 4; j++)
            S[(r0 + i) * 65 + c0 + j] = acc[i][j] * scale;
    __syncthreads();

    // Load V into QV buffer (Q no longer needed)
    #pragma unroll
    for (int f = tid; f < 1024; f += 128) {
        int row = f >> 4;
        int dq  = (f & 15) << 2;
        *(float4*)(QV + row * 64 + dq) =
            *(const float4*)(qkv + base + (size_t)row * (3 * Dq) + 2 * Dq + dq);
    }
    __syncthreads();

    // Row softmax (threads 0..63, one row each; pad 65 => conflict-free)
    if (tid < 64) {
        float* r = S + tid * 65;
        float mx = r[0];
        #pragma unroll 8
        for (int j = 1; j < 64; j++) mx = fmaxf(mx, r[j]);
        float s = 0.f;
        #pragma unroll 8
        for (int j = 0; j < 64; j++) { float e = __expf(r[j] - mx); r[j] = e; s += e; }
        float inv = 1.f / s;
        #pragma unroll 8
        for (int j = 0; j < 64; j++) r[j] *= inv;
    }
    __syncthreads();

    // O = P V
    float o[8][4];
    #pragma unroll
    for (int i = 0; i < 8; i++)
        #pragma unroll
        for (int t = 0; t < 4; t++) o[i][t] = 0.f;

    #pragma unroll 4
    for (int j = 0; j < 64; j++) {
        float p[8], vv[4];
        #pragma unroll
        for (int i = 0; i < 8; i++) p[i] = S[(r0 + i) * 65 + j];
        #pragma unroll
        for (int t = 0; t < 4; t++) vv[t] = QV[j * 64 + c0 + t];
        #pragma unroll
        for (int i = 0; i < 8; i++)
            #pragma unroll
            for (int t = 0; t < 4; t++)
                o[i][t] = fmaf(p[i], vv[t], o[i][t]);
    }

    #pragma unroll
    for (int i = 0; i < 8; i++) {
        float4 o4 = make_float4(o[i][0], o[i][1], o[i][2], o[i][3]);
        *(float4*)(outp + ((size_t)(b * Lq + w * Wq + r0 + i)) * Dq + h * HDq + c0) = o4;
    }
}

// ---------------------------------------------------------------------------
// LayerNorm: one block per row (1024 elems, 256 threads x 4)
// ---------------------------------------------------------------------------
__global__ __launch_bounds__(256, 1)
void layernorm_k(const float* __restrict__ y, const float* __restrict__ gamma,
                 const float* __restrict__ beta, float* __restrict__ out)
{
    __shared__ float r1[8], r2[8];
    const int row = blockIdx.x;
    const int tid = threadIdx.x;
    const float* yr = y + (size_t)row * Dq;
    const int c = tid * 4;

    float4 v = *(const float4*)(yr + c);
    float s = v.x + v.y + v.z + v.w;
    #pragma unroll
    for (int o = 16; o; o >>= 1) s += __shfl_xor_sync(0xffffffffu, s, o);
    if ((tid & 31) == 0) r1[tid >> 5] = s;
    __syncthreads();

    float mean = 0.f;
    #pragma unroll
    for (int i = 0; i < 8; i++) mean += r1[i];
    mean *= (1.f / 1024.f);

    float dx = v.x - mean, dy = v.y - mean, dz = v.z - mean, dw = v.w - mean;
    float ss = dx * dx + dy * dy + dz * dz + dw * dw;
    #pragma unroll
    for (int o = 16; o; o >>= 1) ss += __shfl_xor_sync(0xffffffffu, ss, o);
    if ((tid & 31) == 0) r2[tid >> 5] = ss;
    __syncthreads();

    float var = 0.f;
    #pragma unroll
    for (int i = 0; i < 8; i++) var += r2[i];
    var *= (1.f / 1024.f);
    float inv = rsqrtf(var + 1e-5f);

    float4 g  = *(const float4*)(gamma + c);
    float4 bt = *(const float4*)(beta + c);
    float4 o4;
    o4.x = dx * inv * g.x + bt.x;
    o4.y = dy * inv * g.y + bt.y;
    o4.z = dz * inv * g.z + bt.z;
    o4.w = dw * inv * g.w + bt.w;
    *(float4*)(out + (size_t)row * Dq + c) = o4;
}

// ---------------------------------------------------------------------------
extern "C" void kernel_launch(void* const* d_in, const int* in_sizes, int n_in,
                              void* d_out, int out_size)
{
    const float* x     = (const float*)d_in[0];
    const float* Wqkv  = (const float*)d_in[1];
    const float* bqkv  = (const float*)d_in[2];
    const float* Wproj = (const float*)d_in[3];
    const float* bproj = (const float*)d_in[4];
    const float* gamma = (const float*)d_in[5];
    const float* beta  = (const float*)d_in[6];
    float* out = (float*)d_out;

    float *qkv, *attn, *y;
    cudaGetSymbolAddress((void**)&qkv,  g_qkv);
    cudaGetSymbolAddress((void**)&attn, g_attn);
    cudaGetSymbolAddress((void**)&y,    g_y);

    cudaFuncSetAttribute(win_attn, cudaFuncAttributeMaxDynamicSharedMemorySize, SMEM_ATTN);

    // 1) QKV projection: [16384,1024] x [3072,1024]^T -> [16384,3072]
    sgemm_nt<<<dim3(3072 / BN, Mrows / BM), 256>>>(x, Wqkv, bqkv, nullptr, qkv,
                                                   Mrows, 3 * Dq, Dq);
    // 2) Windowed attention -> [16384,1024]
    win_attn<<<Bq * Hq * (Lq / Wq), 128, SMEM_ATTN>>>(qkv, attn);
    // 3) Output projection + bias + residual -> y
    sgemm_nt<<<dim3(Dq / BN, Mrows / BM), 256>>>(attn, Wproj, bproj, x, y,
                                                 Mrows, Dq, Dq);
    // 4) LayerNorm -> out
    layernorm_k<<<Mrows, 256>>>(y, gamma, beta, out);
}

// round 4
// speedup vs baseline: 3.2107x; 3.2107x over previous
#include <cuda_runtime.h>
#include <cuda_bf16.h>
#include <math.h>
#include <stdint.h>

// Problem constants
#define Bq   4
#define Lq   4096
#define Dq   1024
#define Hq   16
#define Wq   64
#define HDq  64
#define Mrows (Bq*Lq)          // 16384

// Scratch buffers (device globals; allocation is forbidden)
__device__ float g_qkv[(size_t)Mrows * 3 * Dq];   // 192 MB
__device__ float g_attn[(size_t)Mrows * Dq];      // 64 MB
__device__ float g_y[(size_t)Mrows * Dq];         // 64 MB

// ---------------------------------------------------------------------------
// Helpers
// ---------------------------------------------------------------------------
__device__ __forceinline__ uint32_t smem_u32(const void* p) {
    return (uint32_t)__cvta_generic_to_shared(p);
}
__device__ __forceinline__ void cp16(uint32_t s, const void* g) {
    asm volatile("cp.async.cg.shared.global [%0], [%1], 16;" :: "r"(s), "l"(g));
}
__device__ __forceinline__ uint32_t f2tf(float v) {
    uint32_t r;
    asm("cvt.rna.tf32.f32 %0, %1;" : "=r"(r) : "f"(v));
    return r;
}
__device__ __forceinline__ void mma_tf32(float c[4], const uint32_t a[4],
                                         const uint32_t b[2]) {
    asm volatile(
        "mma.sync.aligned.m16n8k8.row.col.f32.tf32.tf32.f32 "
        "{%0,%1,%2,%3}, {%4,%5,%6,%7}, {%8,%9}, {%0,%1,%2,%3};"
        : "+f"(c[0]), "+f"(c[1]), "+f"(c[2]), "+f"(c[3])
        : "r"(a[0]), "r"(a[1]), "r"(a[2]), "r"(a[3]), "r"(b[0]), "r"(b[1]));
}

// ---------------------------------------------------------------------------
// tf32 mma.sync GEMM (NT): C[m][n] = sum_k A[m][k]*B[n][k] + bias[n] (+res)
// CTA 128x128x32, 256 thr (8 warps, 2x4 of 64x32 warp tiles), 3-stage cp.async.
// SMEM tiles padded to stride 36 floats -> conflict-free fragment loads.
// ---------------------------------------------------------------------------
#define BMt 128
#define BNt 128
#define BKt 32
#define PAD_STRIDE 36                         // 32 + 4 floats
#define STG_FLOATS (2 * BMt * PAD_STRIDE)     // 9216 floats = 36864 B / stage
#define GEMM_SMEM (3 * STG_FLOATS * 4)        // 110592 B

__global__ __launch_bounds__(256, 1)
void mma_gemm(const float* __restrict__ A, const float* __restrict__ B,
              const float* __restrict__ bias, const float* __restrict__ res,
              float* __restrict__ C, int N, int K)
{
    extern __shared__ float dsm[];

    const int tid = threadIdx.x;
    const int wid = tid >> 5, lid = tid & 31;
    const int g = lid >> 2, tg = lid & 3;
    const int wm = (wid >> 2) * 64;   // warp m offset within CTA tile
    const int wn = (wid & 3) * 32;    // warp n offset

    const int bn = blockIdx.x, bm = blockIdx.y;
    const float* Ab = A + (size_t)bm * BMt * K;
    const float* Bb = B + (size_t)bn * BNt * K;
    const int NIT = K / BKt;          // 32

    const uint32_t sb = smem_u32(dsm);

    // Stage loader: A tile 128x32 + B tile 128x32, 16B chunks, padded stride.
    auto issue = [&](int it) {
        uint32_t stg = sb + (uint32_t)(it % 3) * (STG_FLOATS * 4);
        const float* Ag = Ab + it * BKt;
        const float* Bg = Bb + it * BKt;
        #pragma unroll
        for (int f = tid; f < 2048; f += 256) {
            int r = (f >> 3) & 127;
            int c = f & 7;
            const float* src;
            uint32_t dst;
            if (f < 1024) {
                src = Ag + (size_t)r * K + c * 4;
                dst = stg + (uint32_t)(r * (PAD_STRIDE * 4) + c * 16);
            } else {
                src = Bg + (size_t)r * K + c * 4;
                dst = stg + (uint32_t)(BMt * PAD_STRIDE * 4 + r * (PAD_STRIDE * 4) + c * 16);
            }
            cp16(dst, src);
        }
        asm volatile("cp.async.commit_group;" ::: "memory");
    };

    float acc[4][4][4];
    #pragma unroll
    for (int i = 0; i < 4; i++)
        #pragma unroll
        for (int j = 0; j < 4; j++)
            #pragma unroll
            for (int t = 0; t < 4; t++) acc[i][j][t] = 0.f;

    issue(0);
    issue(1);

    for (int it = 0; it < NIT; ++it) {
        if (it + 2 < NIT) {
            issue(it + 2);
            asm volatile("cp.async.wait_group 2;" ::: "memory");
        } else if (it + 1 < NIT) {
            asm volatile("cp.async.wait_group 1;" ::: "memory");
        } else {
            asm volatile("cp.async.wait_group 0;" ::: "memory");
        }
        __syncthreads();

        const float* smA = dsm + (size_t)(it % 3) * STG_FLOATS;
        const float* smB = smA + BMt * PAD_STRIDE;

        #pragma unroll
        for (int k0 = 0; k0 < BKt; k0 += 8) {
            uint32_t a[4][4], bf[4][2];
            #pragma unroll
            for (int mi = 0; mi < 4; mi++) {
                const float* p = smA + (wm + 16 * mi + g) * PAD_STRIDE + k0 + tg;
                a[mi][0] = f2tf(p[0]);
                a[mi][1] = f2tf(p[8 * PAD_STRIDE]);
                a[mi][2] = f2tf(p[4]);
                a[mi][3] = f2tf(p[8 * PAD_STRIDE + 4]);
            }
            #pragma unroll
            for (int nj = 0; nj < 4; nj++) {
                const float* p = smB + (wn + 8 * nj + g) * PAD_STRIDE + k0 + tg;
                bf[nj][0] = f2tf(p[0]);
                bf[nj][1] = f2tf(p[4]);
            }
            #pragma unroll
            for (int mi = 0; mi < 4; mi++)
                #pragma unroll
                for (int nj = 0; nj < 4; nj++)
                    mma_tf32(acc[mi][nj], a[mi], bf[nj]);
        }
        __syncthreads();
    }

    // Epilogue: bias (+residual), float2 stores.
    #pragma unroll
    for (int mi = 0; mi < 4; mi++) {
        const int row0 = bm * BMt + wm + 16 * mi + g;
        #pragma unroll
        for (int nj = 0; nj < 4; nj++) {
            const int col = bn * BNt + wn + 8 * nj + 2 * tg;
            float bx = bias[col], by = bias[col + 1];
            float2 o0, o1;
            o0.x = acc[mi][nj][0] + bx; o0.y = acc[mi][nj][1] + by;
            o1.x = acc[mi][nj][2] + bx; o1.y = acc[mi][nj][3] + by;
            if (res) {
                float2 r0 = *(const float2*)(res + (size_t)row0 * N + col);
                float2 r1 = *(const float2*)(res + (size_t)(row0 + 8) * N + col);
                o0.x += r0.x; o0.y += r0.y;
                o1.x += r1.x; o1.y += r1.y;
            }
            *(float2*)(C + (size_t)row0 * N + col) = o0;
            *(float2*)(C + (size_t)(row0 + 8) * N + col) = o1;
        }
    }
}

// ---------------------------------------------------------------------------
// Windowed attention: one CTA per (b, h, window). 128 threads.
// ---------------------------------------------------------------------------
#define SMEM_ATTN ((4096 + 64 * 65 + 64 * 65) * 4)

__global__ __launch_bounds__(128, 1)
void win_attn(const float* __restrict__ qkv, float* __restrict__ outp)
{
    extern __shared__ float sm[];
    float* QV = sm;
    float* Kt = sm + 4096;
    float* S  = sm + 4096 + 64 * 65;

    const int tid = threadIdx.x;
    const int w = blockIdx.x & 63;
    const int h = (blockIdx.x >> 6) & 15;
    const int b = blockIdx.x >> 10;

    const size_t base = ((size_t)(b * Lq + w * Wq)) * (3 * Dq) + h * HDq;

    #pragma unroll
    for (int f = tid; f < 1024; f += 128) {
        int row = f >> 4;
        int dq  = (f & 15) << 2;
        size_t gg = base + (size_t)row * (3 * Dq) + dq;
        *(float4*)(QV + row * 64 + dq) = *(const float4*)(qkv + gg);
        float4 kv = *(const float4*)(qkv + gg + Dq);
        Kt[(dq + 0) * 65 + row] = kv.x;
        Kt[(dq + 1) * 65 + row] = kv.y;
        Kt[(dq + 2) * 65 + row] = kv.z;
        Kt[(dq + 3) * 65 + row] = kv.w;
    }
    __syncthreads();

    const int r0 = (tid >> 4) << 3;
    const int c0 = (tid & 15) << 2;

    float acc[8][4];
    #pragma unroll
    for (int i = 0; i < 8; i++)
        #pragma unroll
        for (int j = 0; j < 4; j++) acc[i][j] = 0.f;

    #pragma unroll 4
    for (int k = 0; k < 64; k++) {
        float a[8], bb[4];
        #pragma unroll
        for (int i = 0; i < 8; i++) a[i] = QV[(r0 + i) * 64 + k];
        #pragma unroll
        for (int j = 0; j < 4; j++) bb[j] = Kt[k * 65 + c0 + j];
        #pragma unroll
        for (int i = 0; i < 8; i++)
            #pragma unroll
            for (int j = 0; j < 4; j++)
                acc[i][j] = fmaf(a[i], bb[j], acc[i][j]);
    }
    const float scale = 0.125f;
    #pragma unroll
    for (int i = 0; i < 8; i++)
        #pragma unroll
        for (int j = 0; j < 4; j++)
            S[(r0 + i) * 65 + c0 + j] = acc[i][j] * scale;
    __syncthreads();

    #pragma unroll
    for (int f = tid; f < 1024; f += 128) {
        int row = f >> 4;
        int dq  = (f & 15) << 2;
        *(float4*)(QV + row * 64 + dq) =
            *(const float4*)(qkv + base + (size_t)row * (3 * Dq) + 2 * Dq + dq);
    }
    __syncthreads();

    if (tid < 64) {
        float* r = S + tid * 65;
        float mx = r[0];
        #pragma unroll 8
        for (int j = 1; j < 64; j++) mx = fmaxf(mx, r[j]);
        float s = 0.f;
        #pragma unroll 8
        for (int j = 0; j < 64; j++) { float e = __expf(r[j] - mx); r[j] = e; s += e; }
        float inv = 1.f / s;
        #pragma unroll 8
        for (int j = 0; j < 64; j++) r[j] *= inv;
    }
    __syncthreads();

    float o[8][4];
    #pragma unroll
    for (int i = 0; i < 8; i++)
        #pragma unroll
        for (int t = 0; t < 4; t++) o[i][t] = 0.f;

    #pragma unroll 4
    for (int j = 0; j < 64; j++) {
        float p[8], vv[4];
        #pragma unroll
        for (int i = 0; i < 8; i++) p[i] = S[(r0 + i) * 65 + j];
        #pragma unroll
        for (int t = 0; t < 4; t++) vv[t] = QV[j * 64 + c0 + t];
        #pragma unroll
        for (int i = 0; i < 8; i++)
            #pragma unroll
            for (int t = 0; t < 4; t++)
                o[i][t] = fmaf(p[i], vv[t], o[i][t]);
    }

    #pragma unroll
    for (int i = 0; i < 8; i++) {
        float4 o4 = make_float4(o[i][0], o[i][1], o[i][2], o[i][3]);
        *(float4*)(outp + ((size_t)(b * Lq + w * Wq + r0 + i)) * Dq + h * HDq + c0) = o4;
    }
}

// ---------------------------------------------------------------------------
// LayerNorm: one block per row (1024 elems, 256 threads x 4)
// ---------------------------------------------------------------------------
__global__ __launch_bounds__(256, 1)
void layernorm_k(const float* __restrict__ y, const float* __restrict__ gamma,
                 const float* __restrict__ beta, float* __restrict__ out)
{
    __shared__ float r1[8], r2[8];
    const int row = blockIdx.x;
    const int tid = threadIdx.x;
    const float* yr = y + (size_t)row * Dq;
    const int c = tid * 4;

    float4 v = *(const float4*)(yr + c);
    float s = v.x + v.y + v.z + v.w;
    #pragma unroll
    for (int o = 16; o; o >>= 1) s += __shfl_xor_sync(0xffffffffu, s, o);
    if ((tid & 31) == 0) r1[tid >> 5] = s;
    __syncthreads();

    float mean = 0.f;
    #pragma unroll
    for (int i = 0; i < 8; i++) mean += r1[i];
    mean *= (1.f / 1024.f);

    float dx = v.x - mean, dy = v.y - mean, dz = v.z - mean, dw = v.w - mean;
    float ss = dx * dx + dy * dy + dz * dz + dw * dw;
    #pragma unroll
    for (int o = 16; o; o >>= 1) ss += __shfl_xor_sync(0xffffffffu, ss, o);
    if ((tid & 31) == 0) r2[tid >> 5] = ss;
    __syncthreads();

    float var = 0.f;
    #pragma unroll
    for (int i = 0; i < 8; i++) var += r2[i];
    var *= (1.f / 1024.f);
    float inv = rsqrtf(var + 1e-5f);

    float4 gm = *(const float4*)(gamma + c);
    float4 bt = *(const float4*)(beta + c);
    float4 o4;
    o4.x = dx * inv * gm.x + bt.x;
    o4.y = dy * inv * gm.y + bt.y;
    o4.z = dz * inv * gm.z + bt.z;
    o4.w = dw * inv * gm.w + bt.w;
    *(float4*)(out + (size_t)row * Dq + c) = o4;
}

// ---------------------------------------------------------------------------
extern "C" void kernel_launch(void* const* d_in, const int* in_sizes, int n_in,
                              void* d_out, int out_size)
{
    const float* x     = (const float*)d_in[0];
    const float* Wqkv  = (const float*)d_in[1];
    const float* bqkv  = (const float*)d_in[2];
    const float* Wproj = (const float*)d_in[3];
    const float* bproj = (const float*)d_in[4];
    const float* gamma = (const float*)d_in[5];
    const float* beta  = (const float*)d_in[6];
    float* out = (float*)d_out;

    float *qkv, *attn, *y;
    cudaGetSymbolAddress((void**)&qkv,  g_qkv);
    cudaGetSymbolAddress((void**)&attn, g_attn);
    cudaGetSymbolAddress((void**)&y,    g_y);

    cudaFuncSetAttribute(mma_gemm, cudaFuncAttributeMaxDynamicSharedMemorySize, GEMM_SMEM);
    cudaFuncSetAttribute(win_attn, cudaFuncAttributeMaxDynamicSharedMemorySize, SMEM_ATTN);

    // 1) QKV projection: [16384,1024] x [3072,1024]^T -> [16384,3072]
    mma_gemm<<<dim3(3 * Dq / BNt, Mrows / BMt), 256, GEMM_SMEM>>>(
        x, Wqkv, bqkv, nullptr, qkv, 3 * Dq, Dq);
    // 2) Windowed attention -> [16384,1024]
    win_attn<<<Bq * Hq * (Lq / Wq), 128, SMEM_ATTN>>>(qkv, attn);
    // 3) Output projection + bias + residual -> y
    mma_gemm<<<dim3(Dq / BNt, Mrows / BMt), 256, GEMM_SMEM>>>(
        attn, Wproj, bproj, x, y, Dq, Dq);
    // 4) LayerNorm -> out
    layernorm_k<<<Mrows, 256>>>(y, gamma, beta, out);
}

// round 5
// speedup vs baseline: 6.2516x; 1.9471x over previous
#include <cuda_runtime.h>
#include <cuda_fp16.h>
#include <math.h>
#include <stdint.h>

// Problem constants
#define Bq   4
#define Lq   4096
#define Dq   1024
#define Hq   16
#define Wq   64
#define HDq  64
#define Mrows (Bq*Lq)          // 16384

// Scratch buffers (device globals)
__device__ __half g_xh[(size_t)Mrows * Dq];          // 32 MB
__device__ __half g_wqkvh[(size_t)3 * Dq * Dq];      // 6 MB
__device__ __half g_wprojh[(size_t)Dq * Dq];         // 2 MB
__device__ __half g_qkvh[(size_t)Mrows * 3 * Dq];    // 96 MB
__device__ __half g_attnh[(size_t)Mrows * Dq];       // 32 MB
__device__ float  g_y[(size_t)Mrows * Dq];           // 64 MB

// ---------------------------------------------------------------------------
// Helpers
// ---------------------------------------------------------------------------
__device__ __forceinline__ uint32_t smem_u32(const void* p) {
    return (uint32_t)__cvta_generic_to_shared(p);
}
__device__ __forceinline__ void cp16(uint32_t s, const void* g) {
    asm volatile("cp.async.cg.shared.global [%0], [%1], 16;" :: "r"(s), "l"(g));
}
__device__ __forceinline__ void ldsm_x4(uint32_t r[4], uint32_t addr) {
    asm volatile("ldmatrix.sync.aligned.m8n8.x4.shared.b16 {%0,%1,%2,%3}, [%4];"
                 : "=r"(r[0]), "=r"(r[1]), "=r"(r[2]), "=r"(r[3]) : "r"(addr));
}
__device__ __forceinline__ void mma_f16(float c[4], const uint32_t a[4],
                                        uint32_t b0, uint32_t b1) {
    asm volatile(
        "mma.sync.aligned.m16n8k16.row.col.f32.f16.f16.f32 "
        "{%0,%1,%2,%3}, {%4,%5,%6,%7}, {%8,%9}, {%0,%1,%2,%3};"
        : "+f"(c[0]), "+f"(c[1]), "+f"(c[2]), "+f"(c[3])
        : "r"(a[0]), "r"(a[1]), "r"(a[2]), "r"(a[3]), "r"(b0), "r"(b1));
}

// ---------------------------------------------------------------------------
// fp32 -> fp16 conversion (grid-stride, 8 elems/thread)
// ---------------------------------------------------------------------------
__global__ __launch_bounds__(256, 1)
void f2h_kernel(const float* __restrict__ src, __half* __restrict__ dst, int n)
{
    int i = (blockIdx.x * 256 + threadIdx.x) * 8;
    if (i >= n) return;
    float4 v0 = *(const float4*)(src + i);
    float4 v1 = *(const float4*)(src + i + 4);
    __half2 h[4];
    h[0] = __floats2half2_rn(v0.x, v0.y);
    h[1] = __floats2half2_rn(v0.z, v0.w);
    h[2] = __floats2half2_rn(v1.x, v1.y);
    h[3] = __floats2half2_rn(v1.z, v1.w);
    *(uint4*)(dst + i) = *(uint4*)h;
}

// ---------------------------------------------------------------------------
// fp16 mma GEMM (NT): C[m][n] = sum_k A[m][k]*B[n][k] + bias[n] (+res)
// CTA 128x128x32(halfs), 256 thr (8 warps 2x4, 64x32 warp tiles), 3-stage
// cp.async. SMEM rows padded to 40 halfs (80 B): ldmatrix conflict-free.
// Output: fp16 (Ch) when Ch != null, else fp32 (Cf) with residual.
// ---------------------------------------------------------------------------
#define BMh 128
#define BNh 128
#define BKh 32
#define HSTR 40                                // halfs per padded row
#define STG_BYTES_H (2 * 128 * HSTR * 2)       // 20480 B per stage
#define GEMM_SMEM_H (3 * STG_BYTES_H)          // 61440 B

__global__ __launch_bounds__(256, 2)
void hgemm(const __half* __restrict__ A, const __half* __restrict__ B,
           const float* __restrict__ bias, const float* __restrict__ res,
           __half* __restrict__ Ch, float* __restrict__ Cf, int N, int K)
{
    extern __shared__ __half hsm[];

    const int tid = threadIdx.x;
    const int wid = tid >> 5, lid = tid & 31;
    const int wm = (wid >> 2) * 64;
    const int wn = (wid & 3) * 32;

    const int bn = blockIdx.x, bm = blockIdx.y;
    const __half* Ab = A + (size_t)bm * BMh * K;
    const __half* Bb = B + (size_t)bn * BNh * K;
    const int NIT = K / BKh;                   // 32 for K=1024

    const uint32_t sb = smem_u32(hsm);

    auto issue = [&](int it) {
        uint32_t stg = sb + (uint32_t)(it % 3) * STG_BYTES_H;
        const __half* Ag = Ab + it * BKh;
        const __half* Bg = Bb + it * BKh;
        #pragma unroll
        for (int f = tid; f < 1024; f += 256) {
            int r = (f >> 2) & 127;
            int c = f & 3;
            const __half* src;
            uint32_t dst;
            if (f < 512) {
                src = Ag + (size_t)r * K + c * 8;
                dst = stg + (uint32_t)(r * 80 + c * 16);
            } else {
                src = Bg + (size_t)r * K + c * 8;
                dst = stg + (uint32_t)(128 * 80 + r * 80 + c * 16);
            }
            cp16(dst, src);
        }
        asm volatile("cp.async.commit_group;" ::: "memory");
    };

    float acc[4][4][4];
    #pragma unroll
    for (int i = 0; i < 4; i++)
        #pragma unroll
        for (int j = 0; j < 4; j++)
            #pragma unroll
            for (int t = 0; t < 4; t++) acc[i][j][t] = 0.f;

    issue(0);
    issue(1);

    // ldmatrix lane address components
    const int a_row = lid & 15;                   // + wm + 16*mi
    const int a_kh  = (lid >> 4) << 3;            // k offset (halfs)
    const int b_row = ((lid >> 4) << 3) + (lid & 7);  // + wn + 16*bj
    const int b_kh  = ((lid >> 3) & 1) << 3;

    for (int it = 0; it < NIT; ++it) {
        if (it + 2 < NIT) {
            issue(it + 2);
            asm volatile("cp.async.wait_group 2;" ::: "memory");
        } else if (it + 1 < NIT) {
            asm volatile("cp.async.wait_group 1;" ::: "memory");
        } else {
            asm volatile("cp.async.wait_group 0;" ::: "memory");
        }
        __syncthreads();

        uint32_t smA = sb + (uint32_t)(it % 3) * STG_BYTES_H;
        uint32_t smB = smA + 128 * 80;

        #pragma unroll
        for (int k16 = 0; k16 < BKh; k16 += 16) {
            uint32_t a[4][4], bf[2][4];
            #pragma unroll
            for (int mi = 0; mi < 4; mi++)
                ldsm_x4(a[mi], smA + (uint32_t)((wm + 16 * mi + a_row) * 80
                                                + (k16 + a_kh) * 2));
            #pragma unroll
            for (int bj = 0; bj < 2; bj++)
                ldsm_x4(bf[bj], smB + (uint32_t)((wn + 16 * bj + b_row) * 80
                                                 + (k16 + b_kh) * 2));
            #pragma unroll
            for (int mi = 0; mi < 4; mi++) {
                #pragma unroll
                for (int nj = 0; nj < 4; nj++) {
                    int bj = nj >> 1, hi = (nj & 1) << 1;
                    mma_f16(acc[mi][nj], a[mi], bf[bj][hi], bf[bj][hi + 1]);
                }
            }
        }
        __syncthreads();
    }

    // Epilogue
    const int g = lid >> 2, tg = lid & 3;
    #pragma unroll
    for (int mi = 0; mi < 4; mi++) {
        const int row0 = bm * BMh + wm + 16 * mi + g;
        #pragma unroll
        for (int nj = 0; nj < 4; nj++) {
            const int col = bn * BNh + wn + nj * 8 + 2 * tg;
            float bx = bias[col], by = bias[col + 1];
            float v0 = acc[mi][nj][0] + bx, v1 = acc[mi][nj][1] + by;
            float v2 = acc[mi][nj][2] + bx, v3 = acc[mi][nj][3] + by;
            if (Ch) {
                *(__half2*)(Ch + (size_t)row0 * N + col) = __floats2half2_rn(v0, v1);
                *(__half2*)(Ch + (size_t)(row0 + 8) * N + col) = __floats2half2_rn(v2, v3);
            } else {
                float2 r0 = *(const float2*)(res + (size_t)row0 * N + col);
                float2 r1 = *(const float2*)(res + (size_t)(row0 + 8) * N + col);
                float2 o0 = make_float2(v0 + r0.x, v1 + r0.y);
                float2 o1 = make_float2(v2 + r1.x, v3 + r1.y);
                *(float2*)(Cf + (size_t)row0 * N + col) = o0;
                *(float2*)(Cf + (size_t)(row0 + 8) * N + col) = o1;
            }
        }
    }
}

// ---------------------------------------------------------------------------
// Windowed attention: one CTA per (b, h, window). 128 threads.
// Reads fp16 qkv, computes fp32 in SMEM, writes fp16 output.
// ---------------------------------------------------------------------------
#define SMEM_ATTN ((4096 + 64 * 65 + 64 * 65) * 4)

__global__ __launch_bounds__(128, 1)
void win_attn(const __half* __restrict__ qkv, __half* __restrict__ outp)
{
    extern __shared__ float sm[];
    float* QV = sm;
    float* Kt = sm + 4096;
    float* S  = sm + 4096 + 64 * 65;

    const int tid = threadIdx.x;
    const int w = blockIdx.x & 63;
    const int h = (blockIdx.x >> 6) & 15;
    const int b = blockIdx.x >> 10;

    const size_t base = ((size_t)(b * Lq + w * Wq)) * (3 * Dq) + h * HDq;

    // Load Q row-major and K transposed (8 halfs = 16B per op)
    #pragma unroll
    for (int f = tid; f < 512; f += 128) {
        int row = f >> 3;
        int dq  = (f & 7) << 3;
        size_t gg = base + (size_t)row * (3 * Dq) + dq;
        uint4 rq = *(const uint4*)(qkv + gg);
        uint4 rk = *(const uint4*)(qkv + gg + Dq);
        const __half2* hq = (const __half2*)&rq;
        const __half2* hk = (const __half2*)&rk;
        #pragma unroll
        for (int t = 0; t < 4; t++) {
            float2 fq = __half22float2(hq[t]);
            QV[row * 64 + dq + 2 * t]     = fq.x;
            QV[row * 64 + dq + 2 * t + 1] = fq.y;
            float2 fk = __half22float2(hk[t]);
            Kt[(dq + 2 * t) * 65 + row]     = fk.x;
            Kt[(dq + 2 * t + 1) * 65 + row] = fk.y;
        }
    }
    __syncthreads();

    const int r0 = (tid >> 4) << 3;
    const int c0 = (tid & 15) << 2;

    float acc[8][4];
    #pragma unroll
    for (int i = 0; i < 8; i++)
        #pragma unroll
        for (int j = 0; j < 4; j++) acc[i][j] = 0.f;

    #pragma unroll 4
    for (int k = 0; k < 64; k++) {
        float a[8], bb[4];
        #pragma unroll
        for (int i = 0; i < 8; i++) a[i] = QV[(r0 + i) * 64 + k];
        #pragma unroll
        for (int j = 0; j < 4; j++) bb[j] = Kt[k * 65 + c0 + j];
        #pragma unroll
        for (int i = 0; i < 8; i++)
            #pragma unroll
            for (int j = 0; j < 4; j++)
                acc[i][j] = fmaf(a[i], bb[j], acc[i][j]);
    }
    const float scale = 0.125f;
    #pragma unroll
    for (int i = 0; i < 8; i++)
        #pragma unroll
        for (int j = 0; j < 4; j++)
            S[(r0 + i) * 65 + c0 + j] = acc[i][j] * scale;
    __syncthreads();

    // Load V into QV
    #pragma unroll
    for (int f = tid; f < 512; f += 128) {
        int row = f >> 3;
        int dq  = (f & 7) << 3;
        uint4 rv = *(const uint4*)(qkv + base + (size_t)row * (3 * Dq) + 2 * Dq + dq);
        const __half2* hv = (const __half2*)&rv;
        #pragma unroll
        for (int t = 0; t < 4; t++) {
            float2 fv = __half22float2(hv[t]);
            QV[row * 64 + dq + 2 * t]     = fv.x;
            QV[row * 64 + dq + 2 * t + 1] = fv.y;
        }
    }
    __syncthreads();

    if (tid < 64) {
        float* r = S + tid * 65;
        float mx = r[0];
        #pragma unroll 8
        for (int j = 1; j < 64; j++) mx = fmaxf(mx, r[j]);
        float s = 0.f;
        #pragma unroll 8
        for (int j = 0; j < 64; j++) { float e = __expf(r[j] - mx); r[j] = e; s += e; }
        float inv = 1.f / s;
        #pragma unroll 8
        for (int j = 0; j < 64; j++) r[j] *= inv;
    }
    __syncthreads();

    float o[8][4];
    #pragma unroll
    for (int i = 0; i < 8; i++)
        #pragma unroll
        for (int t = 0; t < 4; t++) o[i][t] = 0.f;

    #pragma unroll 4
    for (int j = 0; j < 64; j++) {
        float p[8], vv[4];
        #pragma unroll
        for (int i = 0; i < 8; i++) p[i] = S[(r0 + i) * 65 + j];
        #pragma unroll
        for (int t = 0; t < 4; t++) vv[t] = QV[j * 64 + c0 + t];
        #pragma unroll
        for (int i = 0; i < 8; i++)
            #pragma unroll
            for (int t = 0; t < 4; t++)
                o[i][t] = fmaf(p[i], vv[t], o[i][t]);
    }

    #pragma unroll
    for (int i = 0; i < 8; i++) {
        __half2 h0 = __floats2half2_rn(o[i][0], o[i][1]);
        __half2 h1 = __floats2half2_rn(o[i][2], o[i][3]);
        uint2 pk = make_uint2(*(uint32_t*)&h0, *(uint32_t*)&h1);
        *(uint2*)(outp + ((size_t)(b * Lq + w * Wq + r0 + i)) * Dq + h * HDq + c0) = pk;
    }
}

// ---------------------------------------------------------------------------
// LayerNorm: one block per row (1024 elems, 256 threads x 4)
// ---------------------------------------------------------------------------
__global__ __launch_bounds__(256, 1)
void layernorm_k(const float* __restrict__ y, const float* __restrict__ gamma,
                 const float* __restrict__ beta, float* __restrict__ out)
{
    __shared__ float r1[8], r2[8];
    const int row = blockIdx.x;
    const int tid = threadIdx.x;
    const float* yr = y + (size_t)row * Dq;
    const int c = tid * 4;

    float4 v = *(const float4*)(yr + c);
    float s = v.x + v.y + v.z + v.w;
    #pragma unroll
    for (int o = 16; o; o >>= 1) s += __shfl_xor_sync(0xffffffffu, s, o);
    if ((tid & 31) == 0) r1[tid >> 5] = s;
    __syncthreads();

    float mean = 0.f;
    #pragma unroll
    for (int i = 0; i < 8; i++) mean += r1[i];
    mean *= (1.f / 1024.f);

    float dx = v.x - mean, dy = v.y - mean, dz = v.z - mean, dw = v.w - mean;
    float ss = dx * dx + dy * dy + dz * dz + dw * dw;
    #pragma unroll
    for (int o = 16; o; o >>= 1) ss += __shfl_xor_sync(0xffffffffu, ss, o);
    if ((tid & 31) == 0) r2[tid >> 5] = ss;
    __syncthreads();

    float var = 0.f;
    #pragma unroll
    for (int i = 0; i < 8; i++) var += r2[i];
    var *= (1.f / 1024.f);
    float inv = rsqrtf(var + 1e-5f);

    float4 gm = *(const float4*)(gamma + c);
    float4 bt = *(const float4*)(beta + c);
    float4 o4;
    o4.x = dx * inv * gm.x + bt.x;
    o4.y = dy * inv * gm.y + bt.y;
    o4.z = dz * inv * gm.z + bt.z;
    o4.w = dw * inv * gm.w + bt.w;
    *(float4*)(out + (size_t)row * Dq + c) = o4;
}

// ---------------------------------------------------------------------------
extern "C" void kernel_launch(void* const* d_in, const int* in_sizes, int n_in,
                              void* d_out, int out_size)
{
    const float* x     = (const float*)d_in[0];
    const float* Wqkv  = (const float*)d_in[1];
    const float* bqkv  = (const float*)d_in[2];
    const float* Wproj = (const float*)d_in[3];
    const float* bproj = (const float*)d_in[4];
    const float* gamma = (const float*)d_in[5];
    const float* beta  = (const float*)d_in[6];
    float* out = (float*)d_out;

    __half *xh, *wqkvh, *wprojh, *qkvh, *attnh;
    float* y;
    cudaGetSymbolAddress((void**)&xh,     g_xh);
    cudaGetSymbolAddress((void**)&wqkvh,  g_wqkvh);
    cudaGetSymbolAddress((void**)&wprojh, g_wprojh);
    cudaGetSymbolAddress((void**)&qkvh,   g_qkvh);
    cudaGetSymbolAddress((void**)&attnh,  g_attnh);
    cudaGetSymbolAddress((void**)&y,      g_y);

    cudaFuncSetAttribute(hgemm,    cudaFuncAttributeMaxDynamicSharedMemorySize, GEMM_SMEM_H);
    cudaFuncSetAttribute(win_attn, cudaFuncAttributeMaxDynamicSharedMemorySize, SMEM_ATTN);

    // 0) fp32 -> fp16 conversions
    f2h_kernel<<<(Mrows * Dq) / 2048, 256>>>(x, xh, Mrows * Dq);
    f2h_kernel<<<(3 * Dq * Dq) / 2048, 256>>>(Wqkv, wqkvh, 3 * Dq * Dq);
    f2h_kernel<<<(Dq * Dq) / 2048, 256>>>(Wproj, wprojh, Dq * Dq);

    // 1) QKV projection -> fp16 qkv
    hgemm<<<dim3(3 * Dq / BNh, Mrows / BMh), 256, GEMM_SMEM_H>>>(
        xh, wqkvh, bqkv, nullptr, qkvh, nullptr, 3 * Dq, Dq);
    // 2) Windowed attention -> fp16 attn
    win_attn<<<Bq * Hq * (Lq / Wq), 128, SMEM_ATTN>>>(qkvh, attnh);
    // 3) Output projection + bias + residual -> fp32 y
    hgemm<<<dim3(Dq / BNh, Mrows / BMh), 256, GEMM_SMEM_H>>>(
        attnh, wprojh, bproj, x, nullptr, y, Dq, Dq);
    // 4) LayerNorm -> out
    layernorm_k<<<Mrows, 256>>>(y, gamma, beta, out);
}

// round 6
// speedup vs baseline: 6.6571x; 1.0649x over previous
#include <cuda_runtime.h>
#include <cuda_fp16.h>
#include <math.h>
#include <stdint.h>

// Problem constants
#define Bq   4
#define Lq   4096
#define Dq   1024
#define Hq   16
#define Wq   64
#define HDq  64
#define Mrows (Bq*Lq)          // 16384

// Scratch buffers (device globals)
__device__ __half g_xh[(size_t)Mrows * Dq];          // 32 MB
__device__ __half g_wqkvh[(size_t)3 * Dq * Dq];      // 6 MB
__device__ __half g_wprojh[(size_t)Dq * Dq];         // 2 MB
__device__ __half g_qkvh[(size_t)Mrows * 3 * Dq];    // 96 MB
__device__ __half g_attnh[(size_t)Mrows * Dq];       // 32 MB
__device__ float  g_y[(size_t)Mrows * Dq];           // 64 MB

// ---------------------------------------------------------------------------
// Helpers
// ---------------------------------------------------------------------------
__device__ __forceinline__ uint32_t smem_u32(const void* p) {
    return (uint32_t)__cvta_generic_to_shared(p);
}
__device__ __forceinline__ void cp16(uint32_t s, const void* g) {
    asm volatile("cp.async.cg.shared.global [%0], [%1], 16;" :: "r"(s), "l"(g));
}
__device__ __forceinline__ void ldsm_x4(uint32_t r[4], uint32_t addr) {
    asm volatile("ldmatrix.sync.aligned.m8n8.x4.shared.b16 {%0,%1,%2,%3}, [%4];"
                 : "=r"(r[0]), "=r"(r[1]), "=r"(r[2]), "=r"(r[3]) : "r"(addr));
}
__device__ __forceinline__ void mma_f16(float c[4], const uint32_t a[4],
                                        uint32_t b0, uint32_t b1) {
    asm volatile(
        "mma.sync.aligned.m16n8k16.row.col.f32.f16.f16.f32 "
        "{%0,%1,%2,%3}, {%4,%5,%6,%7}, {%8,%9}, {%0,%1,%2,%3};"
        : "+f"(c[0]), "+f"(c[1]), "+f"(c[2]), "+f"(c[3])
        : "r"(a[0]), "r"(a[1]), "r"(a[2]), "r"(a[3]), "r"(b0), "r"(b1));
}

// ---------------------------------------------------------------------------
// fp32 -> fp16 conversion (grid-stride, 8 elems/thread)
// ---------------------------------------------------------------------------
__global__ __launch_bounds__(256, 1)
void f2h_kernel(const float* __restrict__ src, __half* __restrict__ dst, int n)
{
    int i = (blockIdx.x * 256 + threadIdx.x) * 8;
    if (i >= n) return;
    float4 v0 = *(const float4*)(src + i);
    float4 v1 = *(const float4*)(src + i + 4);
    __half2 h[4];
    h[0] = __floats2half2_rn(v0.x, v0.y);
    h[1] = __floats2half2_rn(v0.z, v0.w);
    h[2] = __floats2half2_rn(v1.x, v1.y);
    h[3] = __floats2half2_rn(v1.z, v1.w);
    *(uint4*)(dst + i) = *(uint4*)h;
}

// ---------------------------------------------------------------------------
// fp16 mma GEMM (NT): C[m][n] = sum_k A[m][k]*B[n][k] + bias[n] (+res)
// CTA 128x128x64(halfs), 256 thr (8 warps 2x4, 64x32 warp tiles), 2-stage
// cp.async ping-pong. SMEM rows padded to 72 halfs (144 B): ldmatrix
// conflict-free (144*r mod 128 = 16*r covers all 8 banks).
// Output: fp16 (Ch) when Ch != null, else fp32 (Cf) with residual.
// ---------------------------------------------------------------------------
#define BMh 128
#define BNh 128
#define BKh 64
#define HSTR 72                                // halfs per padded row
#define ROWB (HSTR * 2)                        // 144 bytes per row
#define STG_BYTES_H (2 * 128 * ROWB)           // 36864 B per stage
#define GEMM_SMEM_H (2 * STG_BYTES_H)          // 73728 B

__global__ __launch_bounds__(256, 2)
void hgemm(const __half* __restrict__ A, const __half* __restrict__ B,
           const float* __restrict__ bias, const float* __restrict__ res,
           __half* __restrict__ Ch, float* __restrict__ Cf, int N, int K)
{
    extern __shared__ __half hsm[];

    const int tid = threadIdx.x;
    const int wid = tid >> 5, lid = tid & 31;
    const int wm = (wid >> 2) * 64;
    const int wn = (wid & 3) * 32;

    const int bn = blockIdx.x, bm = blockIdx.y;
    const __half* Ab = A + (size_t)bm * BMh * K;
    const __half* Bb = B + (size_t)bn * BNh * K;
    const int NIT = K / BKh;                   // 16 for K=1024

    const uint32_t sb = smem_u32(hsm);

    // Stage loader: A 128x64h + B 128x64h = 2048 x 16B chunks, 8 per thread.
    auto issue = [&](int it) {
        uint32_t stg = sb + (uint32_t)(it & 1) * STG_BYTES_H;
        const __half* Ag = Ab + it * BKh;
        const __half* Bg = Bb + it * BKh;
        #pragma unroll
        for (int f = tid; f < 2048; f += 256) {
            int r = (f >> 3) & 127;
            int c = f & 7;
            const __half* src;
            uint32_t dst;
            if (f < 1024) {
                src = Ag + (size_t)r * K + c * 8;
                dst = stg + (uint32_t)(r * ROWB + c * 16);
            } else {
                src = Bg + (size_t)r * K + c * 8;
                dst = stg + (uint32_t)(128 * ROWB + r * ROWB + c * 16);
            }
            cp16(dst, src);
        }
        asm volatile("cp.async.commit_group;" ::: "memory");
    };

    float acc[4][4][4];
    #pragma unroll
    for (int i = 0; i < 4; i++)
        #pragma unroll
        for (int j = 0; j < 4; j++)
            #pragma unroll
            for (int t = 0; t < 4; t++) acc[i][j][t] = 0.f;

    issue(0);

    // ldmatrix lane address components
    const int a_row = lid & 15;                       // + wm + 16*mi
    const int a_kh  = (lid >> 4) << 3;                // k offset (halfs)
    const int b_row = ((lid >> 4) << 3) + (lid & 7);  // + wn + 16*bj
    const int b_kh  = ((lid >> 3) & 1) << 3;

    for (int it = 0; it < NIT; ++it) {
        if (it + 1 < NIT) {
            issue(it + 1);
            asm volatile("cp.async.wait_group 1;" ::: "memory");
        } else {
            asm volatile("cp.async.wait_group 0;" ::: "memory");
        }
        __syncthreads();

        uint32_t smA = sb + (uint32_t)(it & 1) * STG_BYTES_H;
        uint32_t smB = smA + 128 * ROWB;

        #pragma unroll
        for (int k16 = 0; k16 < BKh; k16 += 16) {
            uint32_t a[4][4], bf[2][4];
            #pragma unroll
            for (int mi = 0; mi < 4; mi++)
                ldsm_x4(a[mi], smA + (uint32_t)((wm + 16 * mi + a_row) * ROWB
                                                + (k16 + a_kh) * 2));
            #pragma unroll
            for (int bj = 0; bj < 2; bj++)
                ldsm_x4(bf[bj], smB + (uint32_t)((wn + 16 * bj + b_row) * ROWB
                                                 + (k16 + b_kh) * 2));
            #pragma unroll
            for (int mi = 0; mi < 4; mi++) {
                #pragma unroll
                for (int nj = 0; nj < 4; nj++) {
                    int bj = nj >> 1, hi = (nj & 1) << 1;
                    mma_f16(acc[mi][nj], a[mi], bf[bj][hi], bf[bj][hi + 1]);
                }
            }
        }
        __syncthreads();
    }

    // Epilogue
    const int g = lid >> 2, tg = lid & 3;
    #pragma unroll
    for (int mi = 0; mi < 4; mi++) {
        const int row0 = bm * BMh + wm + 16 * mi + g;
        #pragma unroll
        for (int nj = 0; nj < 4; nj++) {
            const int col = bn * BNh + wn + nj * 8 + 2 * tg;
            float bx = bias[col], by = bias[col + 1];
            float v0 = acc[mi][nj][0] + bx, v1 = acc[mi][nj][1] + by;
            float v2 = acc[mi][nj][2] + bx, v3 = acc[mi][nj][3] + by;
            if (Ch) {
                *(__half2*)(Ch + (size_t)row0 * N + col) = __floats2half2_rn(v0, v1);
                *(__half2*)(Ch + (size_t)(row0 + 8) * N + col) = __floats2half2_rn(v2, v3);
            } else {
                float2 r0 = *(const float2*)(res + (size_t)row0 * N + col);
                float2 r1 = *(const float2*)(res + (size_t)(row0 + 8) * N + col);
                float2 o0 = make_float2(v0 + r0.x, v1 + r0.y);
                float2 o1 = make_float2(v2 + r1.x, v3 + r1.y);
                *(float2*)(Cf + (size_t)row0 * N + col) = o0;
                *(float2*)(Cf + (size_t)(row0 + 8) * N + col) = o1;
            }
        }
    }
}

// ---------------------------------------------------------------------------
// Windowed attention: one CTA per (b, h, window). 128 threads.
// Reads fp16 qkv, computes fp32 in SMEM, writes fp16 output.
// ---------------------------------------------------------------------------
#define SMEM_ATTN ((4096 + 64 * 65 + 64 * 65) * 4)

__global__ __launch_bounds__(128, 1)
void win_attn(const __half* __restrict__ qkv, __half* __restrict__ outp)
{
    extern __shared__ float sm[];
    float* QV = sm;
    float* Kt = sm + 4096;
    float* S  = sm + 4096 + 64 * 65;

    const int tid = threadIdx.x;
    const int w = blockIdx.x & 63;
    const int h = (blockIdx.x >> 6) & 15;
    const int b = blockIdx.x >> 10;

    const size_t base = ((size_t)(b * Lq + w * Wq)) * (3 * Dq) + h * HDq;

    #pragma unroll
    for (int f = tid; f < 512; f += 128) {
        int row = f >> 3;
        int dq  = (f & 7) << 3;
        size_t gg = base + (size_t)row * (3 * Dq) + dq;
        uint4 rq = *(const uint4*)(qkv + gg);
        uint4 rk = *(const uint4*)(qkv + gg + Dq);
        const __half2* hq = (const __half2*)&rq;
        const __half2* hk = (const __half2*)&rk;
        #pragma unroll
        for (int t = 0; t < 4; t++) {
            float2 fq = __half22float2(hq[t]);
            QV[row * 64 + dq + 2 * t]     = fq.x;
            QV[row * 64 + dq + 2 * t + 1] = fq.y;
            float2 fk = __half22float2(hk[t]);
            Kt[(dq + 2 * t) * 65 + row]     = fk.x;
            Kt[(dq + 2 * t + 1) * 65 + row] = fk.y;
        }
    }
    __syncthreads();

    const int r0 = (tid >> 4) << 3;
    const int c0 = (tid & 15) << 2;

    float acc[8][4];
    #pragma unroll
    for (int i = 0; i < 8; i++)
        #pragma unroll
        for (int j = 0; j < 4; j++) acc[i][j] = 0.f;

    #pragma unroll 4
    for (int k = 0; k < 64; k++) {
        float a[8], bb[4];
        #pragma unroll
        for (int i = 0; i < 8; i++) a[i] = QV[(r0 + i) * 64 + k];
        #pragma unroll
        for (int j = 0; j < 4; j++) bb[j] = Kt[k * 65 + c0 + j];
        #pragma unroll
        for (int i = 0; i < 8; i++)
            #pragma unroll
            for (int j = 0; j < 4; j++)
                acc[i][j] = fmaf(a[i], bb[j], acc[i][j]);
    }
    const float scale = 0.125f;
    #pragma unroll
    for (int i = 0; i < 8; i++)
        #pragma unroll
        for (int j = 0; j < 4; j++)
            S[(r0 + i) * 65 + c0 + j] = acc[i][j] * scale;
    __syncthreads();

    #pragma unroll
    for (int f = tid; f < 512; f += 128) {
        int row = f >> 3;
        int dq  = (f & 7) << 3;
        uint4 rv = *(const uint4*)(qkv + base + (size_t)row * (3 * Dq) + 2 * Dq + dq);
        const __half2* hv = (const __half2*)&rv;
        #pragma unroll
        for (int t = 0; t < 4; t++) {
            float2 fv = __half22float2(hv[t]);
            QV[row * 64 + dq + 2 * t]     = fv.x;
            QV[row * 64 + dq + 2 * t + 1] = fv.y;
        }
    }
    __syncthreads();

    if (tid < 64) {
        float* r = S + tid * 65;
        float mx = r[0];
        #pragma unroll 8
        for (int j = 1; j < 64; j++) mx = fmaxf(mx, r[j]);
        float s = 0.f;
        #pragma unroll 8
        for (int j = 0; j < 64; j++) { float e = __expf(r[j] - mx); r[j] = e; s += e; }
        float inv = 1.f / s;
        #pragma unroll 8
        for (int j = 0; j < 64; j++) r[j] *= inv;
    }
    __syncthreads();

    float o[8][4];
    #pragma unroll
    for (int i = 0; i < 8; i++)
        #pragma unroll
        for (int t = 0; t < 4; t++) o[i][t] = 0.f;

    #pragma unroll 4
    for (int j = 0; j < 64; j++) {
        float p[8], vv[4];
        #pragma unroll
        for (int i = 0; i < 8; i++) p[i] = S[(r0 + i) * 65 + j];
        #pragma unroll
        for (int t = 0; t < 4; t++) vv[t] = QV[j * 64 + c0 + t];
        #pragma unroll
        for (int i = 0; i < 8; i++)
            #pragma unroll
            for (int t = 0; t < 4; t++)
                o[i][t] = fmaf(p[i], vv[t], o[i][t]);
    }

    #pragma unroll
    for (int i = 0; i < 8; i++) {
        __half2 h0 = __floats2half2_rn(o[i][0], o[i][1]);
        __half2 h1 = __floats2half2_rn(o[i][2], o[i][3]);
        uint2 pk = make_uint2(*(uint32_t*)&h0, *(uint32_t*)&h1);
        *(uint2*)(outp + ((size_t)(b * Lq + w * Wq + r0 + i)) * Dq + h * HDq + c0) = pk;
    }
}

// ---------------------------------------------------------------------------
// LayerNorm: one block per row (1024 elems, 256 threads x 4)
// ---------------------------------------------------------------------------
__global__ __launch_bounds__(256, 1)
void layernorm_k(const float* __restrict__ y, const float* __restrict__ gamma,
                 const float* __restrict__ beta, float* __restrict__ out)
{
    __shared__ float r1[8], r2[8];
    const int row = blockIdx.x;
    const int tid = threadIdx.x;
    const float* yr = y + (size_t)row * Dq;
    const int c = tid * 4;

    float4 v = *(const float4*)(yr + c);
    float s = v.x + v.y + v.z + v.w;
    #pragma unroll
    for (int o = 16; o; o >>= 1) s += __shfl_xor_sync(0xffffffffu, s, o);
    if ((tid & 31) == 0) r1[tid >> 5] = s;
    __syncthreads();

    float mean = 0.f;
    #pragma unroll
    for (int i = 0; i < 8; i++) mean += r1[i];
    mean *= (1.f / 1024.f);

    float dx = v.x - mean, dy = v.y - mean, dz = v.z - mean, dw = v.w - mean;
    float ss = dx * dx + dy * dy + dz * dz + dw * dw;
    #pragma unroll
    for (int o = 16; o; o >>= 1) ss += __shfl_xor_sync(0xffffffffu, ss, o);
    if ((tid & 31) == 0) r2[tid >> 5] = ss;
    __syncthreads();

    float var = 0.f;
    #pragma unroll
    for (int i = 0; i < 8; i++) var += r2[i];
    var *= (1.f / 1024.f);
    float inv = rsqrtf(var + 1e-5f);

    float4 gm = *(const float4*)(gamma + c);
    float4 bt = *(const float4*)(beta + c);
    float4 o4;
    o4.x = dx * inv * gm.x + bt.x;
    o4.y = dy * inv * gm.y + bt.y;
    o4.z = dz * inv * gm.z + bt.z;
    o4.w = dw * inv * gm.w + bt.w;
    *(float4*)(out + (size_t)row * Dq + c) = o4;
}

// ---------------------------------------------------------------------------
extern "C" void kernel_launch(void* const* d_in, const int* in_sizes, int n_in,
                              void* d_out, int out_size)
{
    const float* x     = (const float*)d_in[0];
    const float* Wqkv  = (const float*)d_in[1];
    const float* bqkv  = (const float*)d_in[2];
    const float* Wproj = (const float*)d_in[3];
    const float* bproj = (const float*)d_in[4];
    const float* gamma = (const float*)d_in[5];
    const float* beta  = (const float*)d_in[6];
    float* out = (float*)d_out;

    __half *xh, *wqkvh, *wprojh, *qkvh, *attnh;
    float* y;
    cudaGetSymbolAddress((void**)&xh,     g_xh);
    cudaGetSymbolAddress((void**)&wqkvh,  g_wqkvh);
    cudaGetSymbolAddress((void**)&wprojh, g_wprojh);
    cudaGetSymbolAddress((void**)&qkvh,   g_qkvh);
    cudaGetSymbolAddress((void**)&attnh,  g_attnh);
    cudaGetSymbolAddress((void**)&y,      g_y);

    cudaFuncSetAttribute(hgemm,    cudaFuncAttributeMaxDynamicSharedMemorySize, GEMM_SMEM_H);
    cudaFuncSetAttribute(win_attn, cudaFuncAttributeMaxDynamicSharedMemorySize, SMEM_ATTN);

    // 0) fp32 -> fp16 conversions
    f2h_kernel<<<(Mrows * Dq) / 2048, 256>>>(x, xh, Mrows * Dq);
    f2h_kernel<<<(3 * Dq * Dq) / 2048, 256>>>(Wqkv, wqkvh, 3 * Dq * Dq);
    f2h_kernel<<<(Dq * Dq) / 2048, 256>>>(Wproj, wprojh, Dq * Dq);

    // 1) QKV projection -> fp16 qkv
    hgemm<<<dim3(3 * Dq / BNh, Mrows / BMh), 256, GEMM_SMEM_H>>>(
        xh, wqkvh, bqkv, nullptr, qkvh, nullptr, 3 * Dq, Dq);
    // 2) Windowed attention -> fp16 attn
    win_attn<<<Bq * Hq * (Lq / Wq), 128, SMEM_ATTN>>>(qkvh, attnh);
    // 3) Output projection + bias + residual -> fp32 y
    hgemm<<<dim3(Dq / BNh, Mrows / BMh), 256, GEMM_SMEM_H>>>(
        attnh, wprojh, bproj, x, nullptr, y, Dq, Dq);
    // 4) LayerNorm -> out
    layernorm_k<<<Mrows, 256>>>(y, gamma, beta, out);
}

// round 10
// speedup vs baseline: 7.5628x; 1.1360x over previous
#include <cuda_runtime.h>
#include <cuda_fp16.h>
#include <math.h>
#include <stdint.h>

// Problem constants
#define Bq   4
#define Lq   4096
#define Dq   1024
#define Hq   16
#define Wq   64
#define HDq  64
#define Mrows (Bq*Lq)          // 16384

// Scratch buffers (device globals)
__device__ __half g_xh[(size_t)Mrows * Dq];          // 32 MB
__device__ __half g_wqkvh[(size_t)3 * Dq * Dq];      // 6 MB
__device__ __half g_wprojh[(size_t)Dq * Dq];         // 2 MB
__device__ __half g_qkvh[(size_t)Mrows * 3 * Dq];    // 96 MB
__device__ __half g_attnh[(size_t)Mrows * Dq];       // 32 MB
__device__ float  g_y[(size_t)Mrows * Dq];           // 64 MB

// ---------------------------------------------------------------------------
// Helpers
// ---------------------------------------------------------------------------
__device__ __forceinline__ uint32_t smem_u32(const void* p) {
    return (uint32_t)__cvta_generic_to_shared(p);
}
__device__ __forceinline__ void cp16(uint32_t s, const void* g) {
    asm volatile("cp.async.cg.shared.global [%0], [%1], 16;" :: "r"(s), "l"(g));
}
__device__ __forceinline__ void ldsm_x4(uint32_t r[4], uint32_t addr) {
    asm volatile("ldmatrix.sync.aligned.m8n8.x4.shared.b16 {%0,%1,%2,%3}, [%4];"
                 : "=r"(r[0]), "=r"(r[1]), "=r"(r[2]), "=r"(r[3]) : "r"(addr));
}
__device__ __forceinline__ void ldsm_x4_t(uint32_t r[4], uint32_t addr) {
    asm volatile("ldmatrix.sync.aligned.m8n8.x4.trans.shared.b16 {%0,%1,%2,%3}, [%4];"
                 : "=r"(r[0]), "=r"(r[1]), "=r"(r[2]), "=r"(r[3]) : "r"(addr));
}
__device__ __forceinline__ void mma_f16(float c[4], const uint32_t a[4],
                                        uint32_t b0, uint32_t b1) {
    asm volatile(
        "mma.sync.aligned.m16n8k16.row.col.f32.f16.f16.f32 "
        "{%0,%1,%2,%3}, {%4,%5,%6,%7}, {%8,%9}, {%0,%1,%2,%3};"
        : "+f"(c[0]), "+f"(c[1]), "+f"(c[2]), "+f"(c[3])
        : "r"(a[0]), "r"(a[1]), "r"(a[2]), "r"(a[3]), "r"(b0), "r"(b1));
}
__device__ __forceinline__ uint32_t h2u(float x, float y) {
    __half2 h = __floats2half2_rn(x, y);
    return *(uint32_t*)&h;
}

// ---------------------------------------------------------------------------
// fp32 -> fp16 conversion (grid-stride, 8 elems/thread)
// ---------------------------------------------------------------------------
__global__ __launch_bounds__(256, 1)
void f2h_kernel(const float* __restrict__ src, __half* __restrict__ dst, int n)
{
    int i = (blockIdx.x * 256 + threadIdx.x) * 8;
    if (i >= n) return;
    float4 v0 = *(const float4*)(src + i);
    float4 v1 = *(const float4*)(src + i + 4);
    __half2 h[4];
    h[0] = __floats2half2_rn(v0.x, v0.y);
    h[1] = __floats2half2_rn(v0.z, v0.w);
    h[2] = __floats2half2_rn(v1.x, v1.y);
    h[3] = __floats2half2_rn(v1.z, v1.w);
    *(uint4*)(dst + i) = *(uint4*)h;
}

// ---------------------------------------------------------------------------
// fp16 mma GEMM (NT): C[m][n] = sum_k A[m][k]*B[n][k] + bias[n] (+res)
// CTA 128x128x64(halfs), 256 thr (8 warps 2x4, 64x32 warp tiles), 3-stage
// cp.async. SMEM rows padded to 72 halfs (144 B): ldmatrix conflict-free.
// a-fragments ping-pong so LDSM hides under MMA.
// ---------------------------------------------------------------------------
#define BMh 128
#define BNh 128
#define BKh 64
#define HSTR 72                                // halfs per padded row
#define ROWB (HSTR * 2)                        // 144 bytes per row
#define STG_BYTES_H (2 * 128 * ROWB)           // 36864 B per stage
#define GEMM_SMEM_H (3 * STG_BYTES_H)          // 110592 B

__global__ __launch_bounds__(256, 2)
void hgemm(const __half* __restrict__ A, const __half* __restrict__ B,
           const float* __restrict__ bias, const float* __restrict__ res,
           __half* __restrict__ Ch, float* __restrict__ Cf, int N, int K)
{
    extern __shared__ __half hsm[];

    const int tid = threadIdx.x;
    const int wid = tid >> 5, lid = tid & 31;
    const int wm = (wid >> 2) * 64;
    const int wn = (wid & 3) * 32;

    const int bn = blockIdx.x, bm = blockIdx.y;
    const __half* Ab = A + (size_t)bm * BMh * K;
    const __half* Bb = B + (size_t)bn * BNh * K;
    const int NIT = K / BKh;                   // 16 for K=1024

    const uint32_t sb = smem_u32(hsm);

    auto issue = [&](int it) {
        uint32_t stg = sb + (uint32_t)(it % 3) * STG_BYTES_H;
        const __half* Ag = Ab + it * BKh;
        const __half* Bg = Bb + it * BKh;
        #pragma unroll
        for (int f = tid; f < 2048; f += 256) {
            int r = (f >> 3) & 127;
            int c = f & 7;
            const __half* src;
            uint32_t dst;
            if (f < 1024) {
                src = Ag + (size_t)r * K + c * 8;
                dst = stg + (uint32_t)(r * ROWB + c * 16);
            } else {
                src = Bg + (size_t)r * K + c * 8;
                dst = stg + (uint32_t)(128 * ROWB + r * ROWB + c * 16);
            }
            cp16(dst, src);
        }
        asm volatile("cp.async.commit_group;" ::: "memory");
    };

    float acc[4][4][4];
    #pragma unroll
    for (int i = 0; i < 4; i++)
        #pragma unroll
        for (int j = 0; j < 4; j++)
            #pragma unroll
            for (int t = 0; t < 4; t++) acc[i][j][t] = 0.f;

    issue(0);
    issue(1);

    // ldmatrix lane address components
    const int a_row = lid & 15;                       // + wm + 16*mi
    const int a_kh  = (lid >> 4) << 3;                // k offset (halfs)
    const int b_row = ((lid >> 4) << 3) + (lid & 7);  // + wn + 16*bj
    const int b_kh  = ((lid >> 3) & 1) << 3;

    for (int it = 0; it < NIT; ++it) {
        if (it + 2 < NIT) {
            issue(it + 2);
            asm volatile("cp.async.wait_group 2;" ::: "memory");
        } else if (it + 1 < NIT) {
            asm volatile("cp.async.wait_group 1;" ::: "memory");
        } else {
            asm volatile("cp.async.wait_group 0;" ::: "memory");
        }
        __syncthreads();

        uint32_t smA = sb + (uint32_t)(it % 3) * STG_BYTES_H;
        uint32_t smB = smA + 128 * ROWB;

        #pragma unroll
        for (int k16 = 0; k16 < BKh; k16 += 16) {
            uint32_t bf[2][4], a0[4], a1[4];
            #pragma unroll
            for (int bj = 0; bj < 2; bj++)
                ldsm_x4(bf[bj], smB + (uint32_t)((wn + 16 * bj + b_row) * ROWB
                                                 + (k16 + b_kh) * 2));
            ldsm_x4(a0, smA + (uint32_t)((wm + a_row) * ROWB + (k16 + a_kh) * 2));

            // mi=0 (prefetch mi=1)
            ldsm_x4(a1, smA + (uint32_t)((wm + 16 + a_row) * ROWB + (k16 + a_kh) * 2));
            #pragma unroll
            for (int nj = 0; nj < 4; nj++)
                mma_f16(acc[0][nj], a0, bf[nj >> 1][(nj & 1) << 1],
                        bf[nj >> 1][((nj & 1) << 1) + 1]);
            // mi=1 (prefetch mi=2)
            ldsm_x4(a0, smA + (uint32_t)((wm + 32 + a_row) * ROWB + (k16 + a_kh) * 2));
            #pragma unroll
            for (int nj = 0; nj < 4; nj++)
                mma_f16(acc[1][nj], a1, bf[nj >> 1][(nj & 1) << 1],
                        bf[nj >> 1][((nj & 1) << 1) + 1]);
            // mi=2 (prefetch mi=3)
            ldsm_x4(a1, smA + (uint32_t)((wm + 48 + a_row) * ROWB + (k16 + a_kh) * 2));
            #pragma unroll
            for (int nj = 0; nj < 4; nj++)
                mma_f16(acc[2][nj], a0, bf[nj >> 1][(nj & 1) << 1],
                        bf[nj >> 1][((nj & 1) << 1) + 1]);
            // mi=3
            #pragma unroll
            for (int nj = 0; nj < 4; nj++)
                mma_f16(acc[3][nj], a1, bf[nj >> 1][(nj & 1) << 1],
                        bf[nj >> 1][((nj & 1) << 1) + 1]);
        }
        __syncthreads();
    }

    // Epilogue
    const int g = lid >> 2, tg = lid & 3;
    #pragma unroll
    for (int mi = 0; mi < 4; mi++) {
        const int row0 = bm * BMh + wm + 16 * mi + g;
        #pragma unroll
        for (int nj = 0; nj < 4; nj++) {
            const int col = bn * BNh + wn + nj * 8 + 2 * tg;
            float bx = bias[col], by = bias[col + 1];
            float v0 = acc[mi][nj][0] + bx, v1 = acc[mi][nj][1] + by;
            float v2 = acc[mi][nj][2] + bx, v3 = acc[mi][nj][3] + by;
            if (Ch) {
                *(__half2*)(Ch + (size_t)row0 * N + col) = __floats2half2_rn(v0, v1);
                *(__half2*)(Ch + (size_t)(row0 + 8) * N + col) = __floats2half2_rn(v2, v3);
            } else {
                float2 r0 = *(const float2*)(res + (size_t)row0 * N + col);
                float2 r1 = *(const float2*)(res + (size_t)(row0 + 8) * N + col);
                float2 o0 = make_float2(v0 + r0.x, v1 + r0.y);
                float2 o1 = make_float2(v2 + r1.x, v3 + r1.y);
                *(float2*)(Cf + (size_t)row0 * N + col) = o0;
                *(float2*)(Cf + (size_t)(row0 + 8) * N + col) = o1;
            }
        }
    }
}

// ---------------------------------------------------------------------------
// Tensor-core windowed attention: one CTA per (b, h, window), 4 warps.
// Warp w owns S/O rows [16w, 16w+16). S never leaves registers; softmax via
// quad shuffles; P fp32 acc repacks directly into fp16 a-fragments; V loaded
// as b-fragments via ldmatrix.trans.
// ---------------------------------------------------------------------------
__global__ __launch_bounds__(128, 1)
void win_attn_tc(const __half* __restrict__ qkv, __half* __restrict__ outp)
{
    __shared__ __half Qs[64 * HSTR], Ks[64 * HSTR], Vs[64 * HSTR];

    const int tid = threadIdx.x, wid = tid >> 5, lid = tid & 31;
    const int w = blockIdx.x & 63;
    const int h = (blockIdx.x >> 6) & 15;
    const int b = blockIdx.x >> 10;

    const size_t base = ((size_t)(b * Lq + w * Wq)) * (3 * Dq) + h * HDq;

    // Load Q, K, V tiles (64 rows x 64 halfs each, padded rows of 72 halfs)
    #pragma unroll
    for (int f = tid; f < 512; f += 128) {
        int row = f >> 3;
        int cq = (f & 7) << 3;
        size_t gg = base + (size_t)row * (3 * Dq) + cq;
        *(uint4*)(Qs + row * HSTR + cq) = *(const uint4*)(qkv + gg);
        *(uint4*)(Ks + row * HSTR + cq) = *(const uint4*)(qkv + gg + Dq);
        *(uint4*)(Vs + row * HSTR + cq) = *(const uint4*)(qkv + gg + 2 * Dq);
    }
    __syncthreads();

    const int g = lid >> 2, tg = lid & 3;
    const int m0 = wid * 16;
    const int a_row = lid & 15;
    const int a_kh  = (lid >> 4) << 3;
    const int b_row = ((lid >> 4) << 3) + (lid & 7);
    const int b_kh  = ((lid >> 3) & 1) << 3;

    const uint32_t qb = smem_u32(Qs), kb2_ = smem_u32(Ks), vb = smem_u32(Vs);

    // Phase 1: S = Q K^T  (warp: m16 x n64 x k64)
    float accS[8][4];
    #pragma unroll
    for (int nj = 0; nj < 8; nj++)
        #pragma unroll
        for (int t = 0; t < 4; t++) accS[nj][t] = 0.f;

    #pragma unroll
    for (int kb = 0; kb < 4; kb++) {
        uint32_t a[4];
        ldsm_x4(a, qb + (uint32_t)((m0 + a_row) * ROWB + (kb * 16 + a_kh) * 2));
        #pragma unroll
        for (int bj = 0; bj < 4; bj++) {
            uint32_t bf[4];
            ldsm_x4(bf, kb2_ + (uint32_t)((16 * bj + b_row) * ROWB
                                          + (kb * 16 + b_kh) * 2));
            mma_f16(accS[2 * bj],     a, bf[0], bf[1]);
            mma_f16(accS[2 * bj + 1], a, bf[2], bf[3]);
        }
    }

    // Softmax in registers. Rows: ra = m0+g (c0,c1), rb = m0+g+8 (c2,c3).
    const float scale = 0.125f;
    float mxa = -1e30f, mxb = -1e30f;
    #pragma unroll
    for (int nj = 0; nj < 8; nj++) {
        #pragma unroll
        for (int t = 0; t < 4; t++) accS[nj][t] *= scale;
        mxa = fmaxf(mxa, fmaxf(accS[nj][0], accS[nj][1]));
        mxb = fmaxf(mxb, fmaxf(accS[nj][2], accS[nj][3]));
    }
    mxa = fmaxf(mxa, __shfl_xor_sync(0xffffffffu, mxa, 1));
    mxa = fmaxf(mxa, __shfl_xor_sync(0xffffffffu, mxa, 2));
    mxb = fmaxf(mxb, __shfl_xor_sync(0xffffffffu, mxb, 1));
    mxb = fmaxf(mxb, __shfl_xor_sync(0xffffffffu, mxb, 2));

    float suma = 0.f, sumb = 0.f;
    #pragma unroll
    for (int nj = 0; nj < 8; nj++) {
        accS[nj][0] = __expf(accS[nj][0] - mxa);
        accS[nj][1] = __expf(accS[nj][1] - mxa);
        accS[nj][2] = __expf(accS[nj][2] - mxb);
        accS[nj][3] = __expf(accS[nj][3] - mxb);
        suma += accS[nj][0] + accS[nj][1];
        sumb += accS[nj][2] + accS[nj][3];
    }
    suma += __shfl_xor_sync(0xffffffffu, suma, 1);
    suma += __shfl_xor_sync(0xffffffffu, suma, 2);
    sumb += __shfl_xor_sync(0xffffffffu, sumb, 1);
    sumb += __shfl_xor_sync(0xffffffffu, sumb, 2);
    const float inva = 1.f / suma, invb = 1.f / sumb;

    // Repack P into fp16 a-fragments: kb2-th k16 block <- accS[2kb2], accS[2kb2+1]
    uint32_t pa[4][4];
    #pragma unroll
    for (int kb2 = 0; kb2 < 4; kb2++) {
        pa[kb2][0] = h2u(accS[2 * kb2][0] * inva,     accS[2 * kb2][1] * inva);
        pa[kb2][1] = h2u(accS[2 * kb2][2] * invb,     accS[2 * kb2][3] * invb);
        pa[kb2][2] = h2u(accS[2 * kb2 + 1][0] * inva, accS[2 * kb2 + 1][1] * inva);
        pa[kb2][3] = h2u(accS[2 * kb2 + 1][2] * invb, accS[2 * kb2 + 1][3] * invb);
    }

    // Phase 2: O = P V  (warp: m16 x n64 x k64). V b-frags via ldmatrix.trans.
    float accO[8][4];
    #pragma unroll
    for (int nj = 0; nj < 8; nj++)
        #pragma unroll
        for (int t = 0; t < 4; t++) accO[nj][t] = 0.f;

    const int v_row = ((lid >> 3) & 1) * 8 + (lid & 7);   // + kb2*16
    const int v_col = ((lid >> 4) & 1) * 8;               // + 16*t

    #pragma unroll
    for (int kb2 = 0; kb2 < 4; kb2++) {
        #pragma unroll
        for (int t = 0; t < 4; t++) {
            uint32_t vf[4];
            ldsm_x4_t(vf, vb + (uint32_t)((kb2 * 16 + v_row) * ROWB
                                          + (16 * t + v_col) * 2));
            mma_f16(accO[2 * t],     pa[kb2], vf[0], vf[1]);
            mma_f16(accO[2 * t + 1], pa[kb2], vf[2], vf[3]);
        }
    }

    // Store O rows (fp16)
    const int orow = b * Lq + w * Wq + m0;
    #pragma unroll
    for (int nj = 0; nj < 8; nj++) {
        const int col = h * HDq + 8 * nj + 2 * tg;
        __half2 lo = __floats2half2_rn(accO[nj][0], accO[nj][1]);
        __half2 hi = __floats2half2_rn(accO[nj][2], accO[nj][3]);
        *(__half2*)(outp + (size_t)(orow + g) * Dq + col) = lo;
        *(__half2*)(outp + (size_t)(orow + g + 8) * Dq + col) = hi;
    }
}

// ---------------------------------------------------------------------------
// LayerNorm: one block per row (1024 elems, 256 threads x 4)
// ---------------------------------------------------------------------------
__global__ __launch_bounds__(256, 1)
void layernorm_k(const float* __restrict__ y, const float* __restrict__ gamma,
                 const float* __restrict__ beta, float* __restrict__ out)
{
    __shared__ float r1[8], r2[8];
    const int row = blockIdx.x;
    const int tid = threadIdx.x;
    const float* yr = y + (size_t)row * Dq;
    const int c = tid * 4;

    float4 v = *(const float4*)(yr + c);
    float s = v.x + v.y + v.z + v.w;
    #pragma unroll
    for (int o = 16; o; o >>= 1) s += __shfl_xor_sync(0xffffffffu, s, o);
    if ((tid & 31) == 0) r1[tid >> 5] = s;
    __syncthreads();

    float mean = 0.f;
    #pragma unroll
    for (int i = 0; i < 8; i++) mean += r1[i];
    mean *= (1.f / 1024.f);

    float dx = v.x - mean, dy = v.y - mean, dz = v.z - mean, dw = v.w - mean;
    float ss = dx * dx + dy * dy + dz * dz + dw * dw;
    #pragma unroll
    for (int o = 16; o; o >>= 1) ss += __shfl_xor_sync(0xffffffffu, ss, o);
    if ((tid & 31) == 0) r2[tid >> 5] = ss;
    __syncthreads();

    float var = 0.f;
    #pragma unroll
    for (int i = 0; i < 8; i++) var += r2[i];
    var *= (1.f / 1024.f);
    float inv = rsqrtf(var + 1e-5f);

    float4 gm = *(const float4*)(gamma + c);
    float4 bt = *(const float4*)(beta + c);
    float4 o4;
    o4.x = dx * inv * gm.x + bt.x;
    o4.y = dy * inv * gm.y + bt.y;
    o4.z = dz * inv * gm.z + bt.z;
    o4.w = dw * inv * gm.w + bt.w;
    *(float4*)(out + (size_t)row * Dq + c) = o4;
}

// ---------------------------------------------------------------------------
extern "C" void kernel_launch(void* const* d_in, const int* in_sizes, int n_in,
                              void* d_out, int out_size)
{
    const float* x     = (const float*)d_in[0];
    const float* Wqkv  = (const float*)d_in[1];
    const float* bqkv  = (const float*)d_in[2];
    const float* Wproj = (const float*)d_in[3];
    const float* bproj = (const float*)d_in[4];
    const float* gamma = (const float*)d_in[5];
    const float* beta  = (const float*)d_in[6];
    float* out = (float*)d_out;

    __half *xh, *wqkvh, *wprojh, *qkvh, *attnh;
    float* y;
    cudaGetSymbolAddress((void**)&xh,     g_xh);
    cudaGetSymbolAddress((void**)&wqkvh,  g_wqkvh);
    cudaGetSymbolAddress((void**)&wprojh, g_wprojh);
    cudaGetSymbolAddress((void**)&qkvh,   g_qkvh);
    cudaGetSymbolAddress((void**)&attnh,  g_attnh);
    cudaGetSymbolAddress((void**)&y,      g_y);

    cudaFuncSetAttribute(hgemm, cudaFuncAttributeMaxDynamicSharedMemorySize, GEMM_SMEM_H);

    // 0) fp32 -> fp16 conversions
    f2h_kernel<<<(Mrows * Dq) / 2048, 256>>>(x, xh, Mrows * Dq);
    f2h_kernel<<<(3 * Dq * Dq) / 2048, 256>>>(Wqkv, wqkvh, 3 * Dq * Dq);
    f2h_kernel<<<(Dq * Dq) / 2048, 256>>>(Wproj, wprojh, Dq * Dq);

    // 1) QKV projection -> fp16 qkv
    hgemm<<<dim3(3 * Dq / BNh, Mrows / BMh), 256, GEMM_SMEM_H>>>(
        xh, wqkvh, bqkv, nullptr, qkvh, nullptr, 3 * Dq, Dq);
    // 2) Windowed attention (tensor cores) -> fp16 attn
    win_attn_tc<<<Bq * Hq * (Lq / Wq), 128>>>(qkvh, attnh);
    // 3) Output projection + bias + residual -> fp32 y
    hgemm<<<dim3(Dq / BNh, Mrows / BMh), 256, GEMM_SMEM_H>>>(
        attnh, wprojh, bproj, x, nullptr, y, Dq, Dq);
    // 4) LayerNorm -> out
    layernorm_k<<<Mrows, 256>>>(y, gamma, beta, out);
}